// round 1
// baseline (speedup 1.0000x reference)
#include <cuda_runtime.h>
#include <cstdint>

// MultiTaskMLP fused 3-layer kernel, fp32 with packed fma.rn.f32x2 (FFMA2).
// One CTA = (task t, 64-row block of B). Intermediates live in SMEM/regs only.

namespace {

constexpr int Bdim  = 4096;
constexpr int Tdim  = 128;
constexpr int INdim = 768;
constexpr int Hdim  = 256;
constexpr int BBLK  = 64;
constexpr int KT    = 16;
constexpr int NTHR  = 256;

constexpr int XS_STRIDE = 20;                 // 64 x 16 X tile, padded row
constexpr int HS_STRIDE = 260;                // 64 x 256 H1 tile, padded row
constexpr int XS_SIZE   = BBLK * XS_STRIDE;   // 1280 floats
constexpr int WS_SIZE   = KT * Hdim;          // 4096 floats
constexpr int HS_SIZE   = BBLK * HS_STRIDE;   // 16640 floats
constexpr int SMEM_FLOATS = HS_SIZE + 2 * XS_SIZE + 2 * WS_SIZE;  // 27392
constexpr int SMEM_BYTES  = SMEM_FLOATS * 4;  // 109568 bytes -> 2 CTAs/SM

typedef unsigned long long ull;

__device__ __forceinline__ uint32_t s2u(const void* p) {
    return (uint32_t)__cvta_generic_to_shared(p);
}
__device__ __forceinline__ void cp16(uint32_t dst, const void* src) {
    asm volatile("cp.async.cg.shared.global [%0], [%1], 16;" :: "r"(dst), "l"(src));
}
__device__ __forceinline__ void cp_commit() {
    asm volatile("cp.async.commit_group;" ::: "memory");
}
template <int N>
__device__ __forceinline__ void cp_wait() {
    asm volatile("cp.async.wait_group %0;" :: "n"(N) : "memory");
}

// pack a scalar into both lanes of an f32x2 register pair
__device__ __forceinline__ ull pk2(float x) {
    ull r;
    asm("mov.b64 %0, {%1, %1};" : "=l"(r) : "f"(x));
    return r;
}
// packed dual FMA: d = a * b + d  (2 fp32 lanes per instruction)
__device__ __forceinline__ void fma2(ull& d, ull a, ull b) {
    asm("fma.rn.f32x2 %0, %1, %2, %0;" : "+l"(d) : "l"(a), "l"(b));
}
__device__ __forceinline__ float2 up2(ull v) {
    float2 f;
    asm("mov.b64 {%0, %1}, %2;" : "=f"(f.x), "=f"(f.y) : "l"(v));
    return f;
}

// one k-slice of the 64x256 tile: 8 rows x 8 cols per thread (4 f32x2 pairs)
__device__ __forceinline__ void mma_step(ull (&acc)[8][4], const float* A0,
                                         int astride, int kk,
                                         const float* WB, int c0) {
    ull pa[8];
#pragma unroll
    for (int r = 0; r < 8; r++) pa[r] = pk2(A0[r * astride + kk]);  // warp-uniform broadcast LDS
    float4 w0 = *(const float4*)(WB + kk * Hdim + c0);
    float4 w1 = *(const float4*)(WB + kk * Hdim + 128 + c0);
    ull b00 = ((const ull*)&w0)[0], b01 = ((const ull*)&w0)[1];
    ull b10 = ((const ull*)&w1)[0], b11 = ((const ull*)&w1)[1];
#pragma unroll
    for (int r = 0; r < 8; r++) {
        fma2(acc[r][0], pa[r], b00);
        fma2(acc[r][1], pa[r], b01);
        fma2(acc[r][2], pa[r], b10);
        fma2(acc[r][3], pa[r], b11);
    }
}

__global__ void __launch_bounds__(NTHR, 2)
mlp_fused_kernel(const float* __restrict__ x,  const float* __restrict__ W1,
                 const float* __restrict__ b1, const float* __restrict__ W2,
                 const float* __restrict__ b2, const float* __restrict__ W3,
                 const float* __restrict__ b3, float* __restrict__ out) {
    extern __shared__ float sm[];
    float* Hs  = sm;                    // 64 x 256 relu(layer1), padded
    float* Xs0 = sm + HS_SIZE;
    float* Xs1 = Xs0 + XS_SIZE;
    float* Ws0 = Xs1 + XS_SIZE;         // shared by layer1 (W1) and layer2 (W2)
    float* Ws1 = Ws0 + WS_SIZE;

    const int tid  = threadIdx.x;
    const int t    = blockIdx.y;
    const int gb0  = blockIdx.x * BBLK;
    const int tcol = tid & 31;          // lane
    const int trow = tid >> 5;          // warp id
    const int r0   = trow * 8;          // this thread's 8 rows
    const int c0   = tcol * 4;          // cols c0..c0+3 and c0+128..c0+131

    // ---- stage-load addressing ----
    const int xrow = tid >> 2;
    const int xkq  = (tid & 3) * 4;
    const float*   xsrc  = x + (size_t)(gb0 + xrow) * INdim + xkq;
    const uint32_t xdst0 = s2u(Xs0 + xrow * XS_STRIDE + xkq);
    const uint32_t xdst1 = s2u(Xs1 + xrow * XS_STRIDE + xkq);
    const uint32_t wdst0 = s2u(Ws0);
    const uint32_t wdst1 = s2u(Ws1);

    const float* W1t = W1 + (size_t)t * INdim * Hdim;
    const float* W2t = W2 + (size_t)t * Hdim * Hdim;

    ull acc[8][4];
#pragma unroll
    for (int r = 0; r < 8; r++)
#pragma unroll
        for (int j = 0; j < 4; j++) acc[r][j] = 0ULL;

    auto load_stage1 = [&](int s, int buf) {
        cp16(buf ? xdst1 : xdst0, xsrc + s * KT);
        const uint32_t wd = buf ? wdst1 : wdst0;
#pragma unroll
        for (int m = 0; m < 4; m++) {
            int idx = tid + NTHR * m;
            int k   = idx >> 6;
            int h4  = (idx & 63) * 4;
            cp16(wd + (uint32_t)(k * Hdim + h4) * 4u,
                 W1t + (size_t)(s * KT + k) * Hdim + h4);
        }
    };
    auto load_stage2 = [&](int s, int buf) {
        const uint32_t wd = buf ? wdst1 : wdst0;
#pragma unroll
        for (int m = 0; m < 4; m++) {
            int idx = tid + NTHR * m;
            int k   = idx >> 6;
            int h4  = (idx & 63) * 4;
            cp16(wd + (uint32_t)(k * Hdim + h4) * 4u,
                 W2t + (size_t)(s * KT + k) * Hdim + h4);
        }
    };

    // =================== Layer 1: H1 = relu(X @ W1[t] + b1[t]) ===================
    constexpr int NS1 = INdim / KT;  // 48 stages
    load_stage1(0, 0); cp_commit();
    load_stage1(1, 1); cp_commit();
    for (int s = 0; s < NS1; s++) {
        if (s < NS1 - 1) cp_wait<1>(); else cp_wait<0>();
        __syncthreads();
        const float* XB = (s & 1) ? Xs1 : Xs0;
        const float* WB = (s & 1) ? Ws1 : Ws0;
        const float* A0 = XB + r0 * XS_STRIDE;
#pragma unroll
        for (int kk = 0; kk < KT; kk++)
            mma_step(acc, A0, XS_STRIDE, kk, WB, c0);
        __syncthreads();
        if (s + 2 < NS1) { load_stage1(s + 2, s & 1); cp_commit(); }
    }

    // epilogue 1: bias + relu -> Hs, reset acc
    {
        const float* b1t = b1 + t * Hdim;
#pragma unroll
        for (int ch = 0; ch < 2; ch++) {
            const int cb = ch * 128 + c0;
            const float4 bb = *(const float4*)(b1t + cb);
#pragma unroll
            for (int r = 0; r < 8; r++) {
                float2 lo = up2(acc[r][ch * 2]);
                float2 hi = up2(acc[r][ch * 2 + 1]);
                float4 h;
                h.x = fmaxf(lo.x + bb.x, 0.f);
                h.y = fmaxf(lo.y + bb.y, 0.f);
                h.z = fmaxf(hi.x + bb.z, 0.f);
                h.w = fmaxf(hi.y + bb.w, 0.f);
                *(float4*)(Hs + (r0 + r) * HS_STRIDE + cb) = h;
                acc[r][ch * 2]     = 0ULL;
                acc[r][ch * 2 + 1] = 0ULL;
            }
        }
    }
    __syncthreads();

    // =================== Layer 2: H2 = relu(H1 @ W2[t] + b2[t]) ==================
    constexpr int NS2 = Hdim / KT;  // 16 stages
    load_stage2(0, 0); cp_commit();
    load_stage2(1, 1); cp_commit();
    for (int s = 0; s < NS2; s++) {
        if (s < NS2 - 1) cp_wait<1>(); else cp_wait<0>();
        __syncthreads();
        const float* WB = (s & 1) ? Ws1 : Ws0;
        const float* A0 = Hs + r0 * HS_STRIDE + s * KT;
#pragma unroll
        for (int kk = 0; kk < KT; kk++)
            mma_step(acc, A0, HS_STRIDE, kk, WB, c0);
        __syncthreads();
        if (s + 2 < NS2) { load_stage2(s + 2, s & 1); cp_commit(); }
    }

    // ============ epilogue 2 + layer 3: out = relu(H2) . W3[t] + b3[t] ===========
    {
        const float* b2t = b2 + t * Hdim;
        const float* w3t = W3 + t * Hdim;
        float red[8];
#pragma unroll
        for (int r = 0; r < 8; r++) red[r] = 0.f;
#pragma unroll
        for (int ch = 0; ch < 2; ch++) {
            const int cb = ch * 128 + c0;
            const float4 bb = *(const float4*)(b2t + cb);
            const float4 ww = *(const float4*)(w3t + cb);
#pragma unroll
            for (int r = 0; r < 8; r++) {
                float2 lo = up2(acc[r][ch * 2]);
                float2 hi = up2(acc[r][ch * 2 + 1]);
                red[r] += fmaxf(lo.x + bb.x, 0.f) * ww.x
                        + fmaxf(lo.y + bb.y, 0.f) * ww.y
                        + fmaxf(hi.x + bb.z, 0.f) * ww.z
                        + fmaxf(hi.y + bb.w, 0.f) * ww.w;
            }
        }
#pragma unroll
        for (int r = 0; r < 8; r++) {
#pragma unroll
            for (int m = 16; m >= 1; m >>= 1)
                red[r] += __shfl_xor_sync(0xffffffffu, red[r], m);
        }
        if (tcol == 0) {
            const float bb3 = b3[t];
#pragma unroll
            for (int r = 0; r < 8; r++)
                out[(size_t)(gb0 + r0 + r) * Tdim + t] = red[r] + bb3;
        }
    }
}

}  // namespace

extern "C" void kernel_launch(void* const* d_in, const int* in_sizes, int n_in,
                              void* d_out, int out_size) {
    const float* x  = (const float*)d_in[0];
    const float* W1 = (const float*)d_in[1];
    const float* b1 = (const float*)d_in[2];
    const float* W2 = (const float*)d_in[3];
    const float* b2 = (const float*)d_in[4];
    const float* W3 = (const float*)d_in[5];
    const float* b3 = (const float*)d_in[6];
    float* out = (float*)d_out;

    cudaFuncSetAttribute(mlp_fused_kernel,
                         cudaFuncAttributeMaxDynamicSharedMemorySize, SMEM_BYTES);
    dim3 grid(Bdim / BBLK, Tdim);  // bblk fastest -> wave shares few tasks' W in L2
    mlp_fused_kernel<<<grid, NTHR, SMEM_BYTES>>>(x, W1, b1, W2, b2, W3, b3, out);
}

// round 4
// speedup vs baseline: 1.5233x; 1.5233x over previous
#include <cuda_runtime.h>
#include <cuda_bf16.h>
#include <cstdint>

// MultiTaskMLP via base-ISA bf16 mma.sync (m16n8k16) with hi/lo fp32 emulation.
// tcgen05 is NOT available (harness PTX targets compute_103, not compute_103a).
// One CTA = (task t, 128 rows of B). 8 warps, warp tile 64x64, acc in regs.

namespace {

constexpr int Bdim = 4096, Tdim = 128, INdim = 768, Hdim = 256;
constexpr int MT = 128;        // rows of B per CTA
constexpr int NTHR = 256;      // 8 warps: 2 (row) x 4 (col) of 64x64 tiles
constexpr int KT = 32;         // k elements per pipeline stage
constexpr int NS1 = INdim / KT;  // 24
constexpr int NS2 = Hdim / KT;   // 8

constexpr int AS1 = 40;        // layer-1 A stage tile stride (bf16 elems)
constexpr int BS  = 264;       // B tiles & H1 stride (bf16 elems)

// smem layout (bytes)
constexpr int A_T  = MT * AS1 * 2;        // 10240 one A tensor tile
constexpr int B_T  = KT * BS * 2;         // 16896 one B tensor tile
constexpr int STG1 = 2 * A_T + 2 * B_T;   // 54272 stage buf (Ahi,Alo,Bhi,Blo)
constexpr int H1LO_OFF = MT * BS * 2;     // 67584
constexpr int R1   = 2 * MT * BS * 2;     // 135168 (H1 region; aliases stage1 bufs)
constexpr int STG2 = 2 * B_T;             // 33792 stage buf (Bhi,Blo)
constexpr int SMEM_TOTAL = R1 + 2 * STG2; // 202752

// -------------------- bf16 hi/lo split scratch --------------------
__device__ __nv_bfloat16 g_xhi[(size_t)Bdim * INdim];
__device__ __nv_bfloat16 g_xlo[(size_t)Bdim * INdim];
__device__ __nv_bfloat16 g_w1hi[(size_t)Tdim * INdim * Hdim];
__device__ __nv_bfloat16 g_w1lo[(size_t)Tdim * INdim * Hdim];
__device__ __nv_bfloat16 g_w2hi[(size_t)Tdim * Hdim * Hdim];
__device__ __nv_bfloat16 g_w2lo[(size_t)Tdim * Hdim * Hdim];

// Elementwise split: v -> hi=bf16(v), lo=bf16(v-hi). Layout preserved.
__global__ void split_kernel(const float4* __restrict__ src, int which, int n4) {
    int i = blockIdx.x * 256 + threadIdx.x;
    if (i >= n4) return;
    uint32_t* hi;
    uint32_t* lo;
    if (which == 0)      { hi = (uint32_t*)g_xhi;  lo = (uint32_t*)g_xlo;  }
    else if (which == 1) { hi = (uint32_t*)g_w1hi; lo = (uint32_t*)g_w1lo; }
    else                 { hi = (uint32_t*)g_w2hi; lo = (uint32_t*)g_w2lo; }
    float4 v = src[i];
    __nv_bfloat162 h0, h1, l0, l1;
    h0.x = __float2bfloat16(v.x); h0.y = __float2bfloat16(v.y);
    h1.x = __float2bfloat16(v.z); h1.y = __float2bfloat16(v.w);
    l0.x = __float2bfloat16(v.x - __bfloat162float(h0.x));
    l0.y = __float2bfloat16(v.y - __bfloat162float(h0.y));
    l1.x = __float2bfloat16(v.z - __bfloat162float(h1.x));
    l1.y = __float2bfloat16(v.w - __bfloat162float(h1.y));
    hi[2 * i]     = *(uint32_t*)&h0;
    hi[2 * i + 1] = *(uint32_t*)&h1;
    lo[2 * i]     = *(uint32_t*)&l0;
    lo[2 * i + 1] = *(uint32_t*)&l1;
}

// ------------------------------ PTX helpers ------------------------------
__device__ __forceinline__ uint32_t s2u(const void* p) {
    return (uint32_t)__cvta_generic_to_shared(p);
}
__device__ __forceinline__ void cp16(uint32_t dst, const void* src) {
    asm volatile("cp.async.cg.shared.global [%0], [%1], 16;" :: "r"(dst), "l"(src));
}
__device__ __forceinline__ void cp_commit() {
    asm volatile("cp.async.commit_group;" ::: "memory");
}
template <int N>
__device__ __forceinline__ void cp_wait() {
    asm volatile("cp.async.wait_group %0;" :: "n"(N) : "memory");
}
__device__ __forceinline__ void ldm4(uint32_t (&r)[4], uint32_t a) {
    asm volatile("ldmatrix.sync.aligned.m8n8.x4.shared.b16 {%0,%1,%2,%3}, [%4];"
                 : "=r"(r[0]), "=r"(r[1]), "=r"(r[2]), "=r"(r[3]) : "r"(a));
}
__device__ __forceinline__ void ldm4t(uint32_t (&r)[4], uint32_t a) {
    asm volatile("ldmatrix.sync.aligned.m8n8.x4.trans.shared.b16 {%0,%1,%2,%3}, [%4];"
                 : "=r"(r[0]), "=r"(r[1]), "=r"(r[2]), "=r"(r[3]) : "r"(a));
}
__device__ __forceinline__ void mma16816(float (&d)[4], const uint32_t (&a)[4],
                                         uint32_t b0, uint32_t b1) {
    asm volatile(
        "mma.sync.aligned.m16n8k16.row.col.f32.bf16.bf16.f32 "
        "{%0,%1,%2,%3}, {%4,%5,%6,%7}, {%8,%9}, {%0,%1,%2,%3};"
        : "+f"(d[0]), "+f"(d[1]), "+f"(d[2]), "+f"(d[3])
        : "r"(a[0]), "r"(a[1]), "r"(a[2]), "r"(a[3]), "r"(b0), "r"(b1));
}

// ------------------------------ main kernel ------------------------------
__global__ void __launch_bounds__(NTHR, 1)
mlp_hmma_kernel(const float* __restrict__ b1, const float* __restrict__ b2,
                const float* __restrict__ W3, const float* __restrict__ b3,
                float* __restrict__ out) {
    extern __shared__ char smem[];
    const uint32_t sb = s2u(smem);
    const int tid = threadIdx.x;
    const int lane = tid & 31, w = tid >> 5;
    const int wr = w >> 2, wc = w & 3;      // warp tile (64 rows, 64 cols)
    const int t = blockIdx.y;
    const int gb0 = blockIdx.x * MT;

    // ldmatrix lane geometry (shared by A non-trans and B trans)
    const int lr  = (lane & 7) + 8 * ((lane >> 3) & 1);  // row within 16
    const int lc8 = 8 * (lane >> 4);                      // col8 select

    const __nv_bfloat16* xh  = g_xhi  + (size_t)gb0 * INdim;
    const __nv_bfloat16* xl  = g_xlo  + (size_t)gb0 * INdim;
    const __nv_bfloat16* w1h = g_w1hi + (size_t)t * INdim * Hdim;
    const __nv_bfloat16* w1l = g_w1lo + (size_t)t * INdim * Hdim;
    const __nv_bfloat16* w2h = g_w2hi + (size_t)t * Hdim * Hdim;
    const __nv_bfloat16* w2l = g_w2lo + (size_t)t * Hdim * Hdim;

    float acc[4][8][4];
#pragma unroll
    for (int mi = 0; mi < 4; mi++)
#pragma unroll
        for (int ni = 0; ni < 8; ni++)
#pragma unroll
            for (int r = 0; r < 4; r++) acc[mi][ni][r] = 0.f;

    // stage loaders
    auto ld_stage1 = [&](int s, int b) {
        const uint32_t sbuf = sb + (b ? STG1 : 0);
        const int k0 = s * KT;
#pragma unroll
        for (int it = 0; it < 2; it++) {     // A: 128 rows x 4 chunks, hi+lo
            int idx = it * NTHR + tid;
            int row = idx >> 2, ch = (idx & 3) * 16;
            uint32_t d = sbuf + (uint32_t)(row * (AS1 * 2) + ch);
            cp16(d,       (const char*)(xh + (size_t)row * INdim + k0) + ch);
            cp16(d + A_T, (const char*)(xl + (size_t)row * INdim + k0) + ch);
        }
#pragma unroll
        for (int it = 0; it < 4; it++) {     // B: 32 rows x 32 chunks, hi+lo
            int idx = it * NTHR + tid;
            int row = idx >> 5, ch = (idx & 31) * 16;
            uint32_t d = sbuf + (uint32_t)(2 * A_T + row * (BS * 2) + ch);
            cp16(d,       (const char*)(w1h + (size_t)(k0 + row) * Hdim) + ch);
            cp16(d + B_T, (const char*)(w1l + (size_t)(k0 + row) * Hdim) + ch);
        }
        cp_commit();
    };
    auto ld_stage2 = [&](int s, int b) {
        const uint32_t sbuf = sb + (uint32_t)(R1 + (b ? STG2 : 0));
        const int k0 = s * KT;
#pragma unroll
        for (int it = 0; it < 4; it++) {
            int idx = it * NTHR + tid;
            int row = idx >> 5, ch = (idx & 31) * 16;
            uint32_t d = sbuf + (uint32_t)(row * (BS * 2) + ch);
            cp16(d,       (const char*)(w2h + (size_t)(k0 + row) * Hdim) + ch);
            cp16(d + B_T, (const char*)(w2l + (size_t)(k0 + row) * Hdim) + ch);
        }
        cp_commit();
    };

    // one k16 slab: 3-way split MMAs into acc
    auto do_k16 = [&](uint32_t aHi, uint32_t aLo, int aMiStep,
                      uint32_t bHi, uint32_t bLo) {
        uint32_t ah[4][4], al[4][4];
#pragma unroll
        for (int mi = 0; mi < 4; mi++) {
            ldm4(ah[mi], aHi + (uint32_t)(mi * aMiStep));
            ldm4(al[mi], aLo + (uint32_t)(mi * aMiStep));
        }
#pragma unroll
        for (int ni2 = 0; ni2 < 4; ni2++) {
            uint32_t bh4[4], bl4[4];
            ldm4t(bh4, bHi + (uint32_t)(ni2 * 32));
            ldm4t(bl4, bLo + (uint32_t)(ni2 * 32));
#pragma unroll
            for (int mi = 0; mi < 4; mi++) {
                mma16816(acc[mi][2 * ni2],     ah[mi], bh4[0], bh4[1]);  // hh
                mma16816(acc[mi][2 * ni2 + 1], ah[mi], bh4[2], bh4[3]);
                mma16816(acc[mi][2 * ni2],     al[mi], bh4[0], bh4[1]);  // lh
                mma16816(acc[mi][2 * ni2 + 1], al[mi], bh4[2], bh4[3]);
                mma16816(acc[mi][2 * ni2],     ah[mi], bl4[0], bl4[1]);  // hl
                mma16816(acc[mi][2 * ni2 + 1], ah[mi], bl4[2], bl4[3]);
            }
        }
    };

    // lane-resolved base offsets (bytes)
    const uint32_t aOffL1 = (uint32_t)(((wr * 64 + lr) * AS1 + lc8) * 2);
    const uint32_t bOffW  = (uint32_t)((lr * BS + lc8 + wc * 64) * 2);
    const uint32_t aOffL2 = (uint32_t)(((wr * 64 + lr) * BS + lc8) * 2);

    // ========================= Layer 1 =========================
    ld_stage1(0, 0);
#pragma unroll 2
    for (int s = 0; s < NS1; s++) {
        const int b = s & 1;
        if (s + 1 < NS1) { ld_stage1(s + 1, b ^ 1); cp_wait<1>(); }
        else             { cp_wait<0>(); }
        __syncthreads();
        const uint32_t sbuf = sb + (b ? STG1 : 0);
#pragma unroll
        for (int kk = 0; kk < 2; kk++) {
            do_k16(sbuf + aOffL1 + kk * 32,
                   sbuf + A_T + aOffL1 + kk * 32, 16 * AS1 * 2,
                   sbuf + 2 * A_T + bOffW + (uint32_t)(kk * 16 * BS * 2),
                   sbuf + 2 * A_T + B_T + bOffW + (uint32_t)(kk * 16 * BS * 2));
        }
        __syncthreads();
    }

    // prefetch layer-2 stage 0 so it overlaps epilogue 1
    ld_stage2(0, 0);

    // ===== Epilogue 1: bias+relu, split to bf16 hi/lo in smem (H1) =====
    {
        const float* b1t = b1 + t * Hdim;
#pragma unroll
        for (int mi = 0; mi < 4; mi++)
#pragma unroll
            for (int ni = 0; ni < 8; ni++) {
                const int colb = wc * 64 + ni * 8 + (lane & 3) * 2;
                const float2 bb = *(const float2*)(b1t + colb);
#pragma unroll
                for (int h = 0; h < 2; h++) {
                    const int row = wr * 64 + mi * 16 + (lane >> 2) + 8 * h;
                    float v0 = fmaxf(acc[mi][ni][2 * h]     + bb.x, 0.f);
                    float v1 = fmaxf(acc[mi][ni][2 * h + 1] + bb.y, 0.f);
                    __nv_bfloat162 hp, lp;
                    hp.x = __float2bfloat16(v0);
                    hp.y = __float2bfloat16(v1);
                    lp.x = __float2bfloat16(v0 - __bfloat162float(hp.x));
                    lp.y = __float2bfloat16(v1 - __bfloat162float(hp.y));
                    const uint32_t off = (uint32_t)((row * BS + colb) * 2);
                    *(uint32_t*)(smem + off)            = *(uint32_t*)&hp;
                    *(uint32_t*)(smem + H1LO_OFF + off) = *(uint32_t*)&lp;
                    acc[mi][ni][2 * h] = 0.f;
                    acc[mi][ni][2 * h + 1] = 0.f;
                }
            }
    }

    // ========================= Layer 2 =========================
#pragma unroll 2
    for (int s = 0; s < NS2; s++) {
        const int b = s & 1;
        if (s + 1 < NS2) { ld_stage2(s + 1, b ^ 1); cp_wait<1>(); }
        else             { cp_wait<0>(); }
        __syncthreads();   // also orders epilogue-1 H1 writes before reads
        const uint32_t sbuf = sb + (uint32_t)(R1 + (b ? STG2 : 0));
#pragma unroll
        for (int kk = 0; kk < 2; kk++) {
            do_k16(sb + aOffL2 + (uint32_t)((s * 32 + kk * 16) * 2),
                   sb + H1LO_OFF + aOffL2 + (uint32_t)((s * 32 + kk * 16) * 2),
                   16 * BS * 2,
                   sbuf + bOffW + (uint32_t)(kk * 16 * BS * 2),
                   sbuf + B_T + bOffW + (uint32_t)(kk * 16 * BS * 2));
        }
        __syncthreads();
    }

    // ======= Epilogue 2 + Layer 3: out = relu(H2).W3 + b3 =======
    {
        const float* b2t = b2 + t * Hdim;
        const float* w3t = W3 + t * Hdim;
        float p[4][2];
#pragma unroll
        for (int mi = 0; mi < 4; mi++) { p[mi][0] = 0.f; p[mi][1] = 0.f; }
#pragma unroll
        for (int ni = 0; ni < 8; ni++) {
            const int colb = wc * 64 + ni * 8 + (lane & 3) * 2;
            const float2 bb = *(const float2*)(b2t + colb);
            const float2 ww = *(const float2*)(w3t + colb);
#pragma unroll
            for (int mi = 0; mi < 4; mi++)
#pragma unroll
                for (int h = 0; h < 2; h++) {
                    p[mi][h] += fmaxf(acc[mi][ni][2 * h]     + bb.x, 0.f) * ww.x
                              + fmaxf(acc[mi][ni][2 * h + 1] + bb.y, 0.f) * ww.y;
                }
        }
        float* red = (float*)(smem + R1);   // [128][4], staging dead after loop
#pragma unroll
        for (int mi = 0; mi < 4; mi++)
#pragma unroll
            for (int h = 0; h < 2; h++) {
                float v = p[mi][h];
                v += __shfl_xor_sync(0xffffffffu, v, 1);
                v += __shfl_xor_sync(0xffffffffu, v, 2);
                if ((lane & 3) == 0) {
                    const int row = wr * 64 + mi * 16 + (lane >> 2) + 8 * h;
                    red[row * 4 + wc] = v;
                }
            }
        __syncthreads();
        if (tid < MT) {
            float s4 = red[tid * 4] + red[tid * 4 + 1] +
                       red[tid * 4 + 2] + red[tid * 4 + 3] + __ldg(b3 + t);
            out[(size_t)(gb0 + tid) * Tdim + t] = s4;
        }
    }
}

}  // namespace

extern "C" void kernel_launch(void* const* d_in, const int* in_sizes, int n_in,
                              void* d_out, int out_size) {
    const float* x  = (const float*)d_in[0];
    const float* W1 = (const float*)d_in[1];
    const float* b1 = (const float*)d_in[2];
    const float* W2 = (const float*)d_in[3];
    const float* b2 = (const float*)d_in[4];
    const float* W3 = (const float*)d_in[5];
    const float* b3 = (const float*)d_in[6];
    float* out = (float*)d_out;

    const int nx  = Bdim * INdim / 4;
    const int nw1 = Tdim * INdim * Hdim / 4;
    const int nw2 = Tdim * Hdim * Hdim / 4;
    split_kernel<<<(nx  + 255) / 256, 256>>>((const float4*)x,  0, nx);
    split_kernel<<<(nw1 + 255) / 256, 256>>>((const float4*)W1, 1, nw1);
    split_kernel<<<(nw2 + 255) / 256, 256>>>((const float4*)W2, 2, nw2);

    cudaFuncSetAttribute(mlp_hmma_kernel,
                         cudaFuncAttributeMaxDynamicSharedMemorySize, SMEM_TOTAL);
    dim3 grid(Bdim / MT, Tdim);  // b-block fastest: wave shares few tasks' W in L2
    mlp_hmma_kernel<<<grid, NTHR, SMEM_TOTAL>>>(b1, b2, W3, b3, out);
}

// round 9
// speedup vs baseline: 2.3853x; 1.5658x over previous
#include <cuda_runtime.h>
#include <cuda_bf16.h>
#include <cstdint>

// MultiTaskMLP via base-ISA bf16 mma.sync (m16n8k16) with hi/lo fp32 emulation.
// tcgen05 is NOT available (harness PTX targets compute_103, not compute_103a).
// One CTA = (task t, 128 rows of B). 8 warps, warp tile 64x64, acc in regs.

namespace {

constexpr int Bdim = 4096, Tdim = 128, INdim = 768, Hdim = 256;
constexpr int MT = 128;        // rows of B per CTA
constexpr int NTHR = 256;      // 8 warps: 2 (row) x 4 (col) of 64x64 tiles
constexpr int KT = 32;         // k elements per pipeline stage
constexpr int NS1 = INdim / KT;  // 24
constexpr int NS2 = Hdim / KT;   // 8

constexpr int AS1 = 40;        // layer-1 A stage tile stride (bf16 elems)
constexpr int BS  = 264;       // B tiles & H1 stride (bf16 elems)

// smem layout (bytes)
constexpr int A_T  = MT * AS1 * 2;        // 10240 one A tensor tile
constexpr int B_T  = KT * BS * 2;         // 16896 one B tensor tile
constexpr int STG1 = 2 * A_T + 2 * B_T;   // 54272 stage buf (Ahi,Alo,Bhi,Blo)
constexpr int H1LO_OFF = MT * BS * 2;     // 67584
constexpr int R1   = 2 * MT * BS * 2;     // 135168 (H1 region; aliases stage1 bufs)
constexpr int STG2 = 2 * B_T;             // 33792 stage buf (Bhi,Blo)
constexpr int SMEM_TOTAL = R1 + 2 * STG2; // 202752

// -------------------- bf16 hi/lo split scratch --------------------
__device__ __nv_bfloat16 g_xhi[(size_t)Bdim * INdim];
__device__ __nv_bfloat16 g_xlo[(size_t)Bdim * INdim];
__device__ __nv_bfloat16 g_w1hi[(size_t)Tdim * INdim * Hdim];
__device__ __nv_bfloat16 g_w1lo[(size_t)Tdim * INdim * Hdim];
__device__ __nv_bfloat16 g_w2hi[(size_t)Tdim * Hdim * Hdim];
__device__ __nv_bfloat16 g_w2lo[(size_t)Tdim * Hdim * Hdim];

// Elementwise split: v -> hi=bf16(v), lo=bf16(v-hi). Layout preserved.
__global__ void split_kernel(const float4* __restrict__ src, int which, int n4) {
    int i = blockIdx.x * 256 + threadIdx.x;
    if (i >= n4) return;
    uint32_t* hi;
    uint32_t* lo;
    if (which == 0)      { hi = (uint32_t*)g_xhi;  lo = (uint32_t*)g_xlo;  }
    else if (which == 1) { hi = (uint32_t*)g_w1hi; lo = (uint32_t*)g_w1lo; }
    else                 { hi = (uint32_t*)g_w2hi; lo = (uint32_t*)g_w2lo; }
    float4 v = src[i];
    __nv_bfloat162 h0, h1, l0, l1;
    h0.x = __float2bfloat16(v.x); h0.y = __float2bfloat16(v.y);
    h1.x = __float2bfloat16(v.z); h1.y = __float2bfloat16(v.w);
    l0.x = __float2bfloat16(v.x - __bfloat162float(h0.x));
    l0.y = __float2bfloat16(v.y - __bfloat162float(h0.y));
    l1.x = __float2bfloat16(v.z - __bfloat162float(h1.x));
    l1.y = __float2bfloat16(v.w - __bfloat162float(h1.y));
    hi[2 * i]     = *(uint32_t*)&h0;
    hi[2 * i + 1] = *(uint32_t*)&h1;
    lo[2 * i]     = *(uint32_t*)&l0;
    lo[2 * i + 1] = *(uint32_t*)&l1;
}

// ------------------------------ PTX helpers ------------------------------
__device__ __forceinline__ uint32_t s2u(const void* p) {
    return (uint32_t)__cvta_generic_to_shared(p);
}
__device__ __forceinline__ void cp16(uint32_t dst, const void* src) {
    asm volatile("cp.async.cg.shared.global [%0], [%1], 16;" :: "r"(dst), "l"(src));
}
__device__ __forceinline__ void cp_commit() {
    asm volatile("cp.async.commit_group;" ::: "memory");
}
template <int N>
__device__ __forceinline__ void cp_wait() {
    asm volatile("cp.async.wait_group %0;" :: "n"(N) : "memory");
}
__device__ __forceinline__ void ldm4(uint32_t (&r)[4], uint32_t a) {
    asm volatile("ldmatrix.sync.aligned.m8n8.x4.shared.b16 {%0,%1,%2,%3}, [%4];"
                 : "=r"(r[0]), "=r"(r[1]), "=r"(r[2]), "=r"(r[3]) : "r"(a));
}
__device__ __forceinline__ void ldm4t(uint32_t (&r)[4], uint32_t a) {
    asm volatile("ldmatrix.sync.aligned.m8n8.x4.trans.shared.b16 {%0,%1,%2,%3}, [%4];"
                 : "=r"(r[0]), "=r"(r[1]), "=r"(r[2]), "=r"(r[3]) : "r"(a));
}
__device__ __forceinline__ void mma16816(float (&d)[4], const uint32_t (&a)[4],
                                         uint32_t b0, uint32_t b1) {
    asm volatile(
        "mma.sync.aligned.m16n8k16.row.col.f32.bf16.bf16.f32 "
        "{%0,%1,%2,%3}, {%4,%5,%6,%7}, {%8,%9}, {%0,%1,%2,%3};"
        : "+f"(d[0]), "+f"(d[1]), "+f"(d[2]), "+f"(d[3])
        : "r"(a[0]), "r"(a[1]), "r"(a[2]), "r"(a[3]), "r"(b0), "r"(b1));
}

// ------------------------------ main kernel ------------------------------
__global__ void __launch_bounds__(NTHR, 1)
mlp_hmma_kernel(const float* __restrict__ b1, const float* __restrict__ b2,
                const float* __restrict__ W3, const float* __restrict__ b3,
                float* __restrict__ out) {
    extern __shared__ char smem[];
    const uint32_t sb = s2u(smem);
    const int tid = threadIdx.x;
    const int lane = tid & 31, w = tid >> 5;
    const int wr = w >> 2, wc = w & 3;      // warp tile (64 rows, 64 cols)
    const int t = blockIdx.y;
    const int gb0 = blockIdx.x * MT;

    // ldmatrix lane geometry (shared by A non-trans and B trans)
    const int lr  = (lane & 7) + 8 * ((lane >> 3) & 1);  // row within 16
    const int lc8 = 8 * (lane >> 4);                      // col8 select

    const __nv_bfloat16* xh  = g_xhi  + (size_t)gb0 * INdim;
    const __nv_bfloat16* xl  = g_xlo  + (size_t)gb0 * INdim;
    const __nv_bfloat16* w1h = g_w1hi + (size_t)t * INdim * Hdim;
    const __nv_bfloat16* w1l = g_w1lo + (size_t)t * INdim * Hdim;
    const __nv_bfloat16* w2h = g_w2hi + (size_t)t * Hdim * Hdim;
    const __nv_bfloat16* w2l = g_w2lo + (size_t)t * Hdim * Hdim;

    float acc[4][8][4];
#pragma unroll
    for (int mi = 0; mi < 4; mi++)
#pragma unroll
        for (int ni = 0; ni < 8; ni++)
#pragma unroll
            for (int r = 0; r < 4; r++) acc[mi][ni][r] = 0.f;

    // stage loaders
    auto ld_stage1 = [&](int s, int b) {
        const uint32_t sbuf = sb + (b ? STG1 : 0);
        const int k0 = s * KT;
#pragma unroll
        for (int it = 0; it < 2; it++) {     // A: 128 rows x 4 chunks, hi+lo
            int idx = it * NTHR + tid;
            int row = idx >> 2, ch = (idx & 3) * 16;
            uint32_t d = sbuf + (uint32_t)(row * (AS1 * 2) + ch);
            cp16(d,       (const char*)(xh + (size_t)row * INdim + k0) + ch);
            cp16(d + A_T, (const char*)(xl + (size_t)row * INdim + k0) + ch);
        }
#pragma unroll
        for (int it = 0; it < 4; it++) {     // B: 32 rows x 32 chunks, hi+lo
            int idx = it * NTHR + tid;
            int row = idx >> 5, ch = (idx & 31) * 16;
            uint32_t d = sbuf + (uint32_t)(2 * A_T + row * (BS * 2) + ch);
            cp16(d,       (const char*)(w1h + (size_t)(k0 + row) * Hdim) + ch);
            cp16(d + B_T, (const char*)(w1l + (size_t)(k0 + row) * Hdim) + ch);
        }
        cp_commit();
    };
    auto ld_stage2 = [&](int s, int b) {
        const uint32_t sbuf = sb + (uint32_t)(R1 + (b ? STG2 : 0));
        const int k0 = s * KT;
#pragma unroll
        for (int it = 0; it < 4; it++) {
            int idx = it * NTHR + tid;
            int row = idx >> 5, ch = (idx & 31) * 16;
            uint32_t d = sbuf + (uint32_t)(row * (BS * 2) + ch);
            cp16(d,       (const char*)(w2h + (size_t)(k0 + row) * Hdim) + ch);
            cp16(d + B_T, (const char*)(w2l + (size_t)(k0 + row) * Hdim) + ch);
        }
        cp_commit();
    };

    // one k16 slab: 3-way split MMAs into acc
    auto do_k16 = [&](uint32_t aHi, uint32_t aLo, int aMiStep,
                      uint32_t bHi, uint32_t bLo) {
        uint32_t ah[4][4], al[4][4];
#pragma unroll
        for (int mi = 0; mi < 4; mi++) {
            ldm4(ah[mi], aHi + (uint32_t)(mi * aMiStep));
            ldm4(al[mi], aLo + (uint32_t)(mi * aMiStep));
        }
#pragma unroll
        for (int ni2 = 0; ni2 < 4; ni2++) {
            uint32_t bh4[4], bl4[4];
            ldm4t(bh4, bHi + (uint32_t)(ni2 * 32));
            ldm4t(bl4, bLo + (uint32_t)(ni2 * 32));
#pragma unroll
            for (int mi = 0; mi < 4; mi++) {
                mma16816(acc[mi][2 * ni2],     ah[mi], bh4[0], bh4[1]);  // hh
                mma16816(acc[mi][2 * ni2 + 1], ah[mi], bh4[2], bh4[3]);
                mma16816(acc[mi][2 * ni2],     al[mi], bh4[0], bh4[1]);  // lh
                mma16816(acc[mi][2 * ni2 + 1], al[mi], bh4[2], bh4[3]);
                mma16816(acc[mi][2 * ni2],     ah[mi], bl4[0], bl4[1]);  // hl
                mma16816(acc[mi][2 * ni2 + 1], ah[mi], bl4[2], bl4[3]);
            }
        }
    };

    // lane-resolved base offsets (bytes)
    const uint32_t aOffL1 = (uint32_t)(((wr * 64 + lr) * AS1 + lc8) * 2);
    const uint32_t bOffW  = (uint32_t)((lr * BS + lc8 + wc * 64) * 2);
    const uint32_t aOffL2 = (uint32_t)(((wr * 64 + lr) * BS + lc8) * 2);

    // ========================= Layer 1 =========================
    ld_stage1(0, 0);
#pragma unroll 2
    for (int s = 0; s < NS1; s++) {
        const int b = s & 1;
        if (s + 1 < NS1) { ld_stage1(s + 1, b ^ 1); cp_wait<1>(); }
        else             { cp_wait<0>(); }
        __syncthreads();
        const uint32_t sbuf = sb + (b ? STG1 : 0);
#pragma unroll
        for (int kk = 0; kk < 2; kk++) {
            do_k16(sbuf + aOffL1 + kk * 32,
                   sbuf + A_T + aOffL1 + kk * 32, 16 * AS1 * 2,
                   sbuf + 2 * A_T + bOffW + (uint32_t)(kk * 16 * BS * 2),
                   sbuf + 2 * A_T + B_T + bOffW + (uint32_t)(kk * 16 * BS * 2));
        }
        __syncthreads();
    }

    // prefetch layer-2 stage 0 so it overlaps epilogue 1
    ld_stage2(0, 0);

    // ===== Epilogue 1: bias+relu, split to bf16 hi/lo in smem (H1) =====
    {
        const float* b1t = b1 + t * Hdim;
#pragma unroll
        for (int mi = 0; mi < 4; mi++)
#pragma unroll
            for (int ni = 0; ni < 8; ni++) {
                const int colb = wc * 64 + ni * 8 + (lane & 3) * 2;
                const float2 bb = *(const float2*)(b1t + colb);
#pragma unroll
                for (int h = 0; h < 2; h++) {
                    const int row = wr * 64 + mi * 16 + (lane >> 2) + 8 * h;
                    float v0 = fmaxf(acc[mi][ni][2 * h]     + bb.x, 0.f);
                    float v1 = fmaxf(acc[mi][ni][2 * h + 1] + bb.y, 0.f);
                    __nv_bfloat162 hp, lp;
                    hp.x = __float2bfloat16(v0);
                    hp.y = __float2bfloat16(v1);
                    lp.x = __float2bfloat16(v0 - __bfloat162float(hp.x));
                    lp.y = __float2bfloat16(v1 - __bfloat162float(hp.y));
                    const uint32_t off = (uint32_t)((row * BS + colb) * 2);
                    *(uint32_t*)(smem + off)            = *(uint32_t*)&hp;
                    *(uint32_t*)(smem + H1LO_OFF + off) = *(uint32_t*)&lp;
                    acc[mi][ni][2 * h] = 0.f;
                    acc[mi][ni][2 * h + 1] = 0.f;
                }
            }
    }

    // ========================= Layer 2 =========================
#pragma unroll 2
    for (int s = 0; s < NS2; s++) {
        const int b = s & 1;
        if (s + 1 < NS2) { ld_stage2(s + 1, b ^ 1); cp_wait<1>(); }
        else             { cp_wait<0>(); }
        __syncthreads();   // also orders epilogue-1 H1 writes before reads
        const uint32_t sbuf = sb + (uint32_t)(R1 + (b ? STG2 : 0));
#pragma unroll
        for (int kk = 0; kk < 2; kk++) {
            do_k16(sb + aOffL2 + (uint32_t)((s * 32 + kk * 16) * 2),
                   sb + H1LO_OFF + aOffL2 + (uint32_t)((s * 32 + kk * 16) * 2),
                   16 * BS * 2,
                   sbuf + bOffW + (uint32_t)(kk * 16 * BS * 2),
                   sbuf + B_T + bOffW + (uint32_t)(kk * 16 * BS * 2));
        }
        __syncthreads();
    }

    // ======= Epilogue 2 + Layer 3: out = relu(H2).W3 + b3 =======
    {
        const float* b2t = b2 + t * Hdim;
        const float* w3t = W3 + t * Hdim;
        float p[4][2];
#pragma unroll
        for (int mi = 0; mi < 4; mi++) { p[mi][0] = 0.f; p[mi][1] = 0.f; }
#pragma unroll
        for (int ni = 0; ni < 8; ni++) {
            const int colb = wc * 64 + ni * 8 + (lane & 3) * 2;
            const float2 bb = *(const float2*)(b2t + colb);
            const float2 ww = *(const float2*)(w3t + colb);
#pragma unroll
            for (int mi = 0; mi < 4; mi++)
#pragma unroll
                for (int h = 0; h < 2; h++) {
                    p[mi][h] += fmaxf(acc[mi][ni][2 * h]     + bb.x, 0.f) * ww.x
                              + fmaxf(acc[mi][ni][2 * h + 1] + bb.y, 0.f) * ww.y;
                }
        }
        float* red = (float*)(smem + R1);   // [128][4], staging dead after loop
#pragma unroll
        for (int mi = 0; mi < 4; mi++)
#pragma unroll
            for (int h = 0; h < 2; h++) {
                float v = p[mi][h];
                v += __shfl_xor_sync(0xffffffffu, v, 1);
                v += __shfl_xor_sync(0xffffffffu, v, 2);
                if ((lane & 3) == 0) {
                    const int row = wr * 64 + mi * 16 + (lane >> 2) + 8 * h;
                    red[row * 4 + wc] = v;
                }
            }
        __syncthreads();
        if (tid < MT) {
            float s4 = red[tid * 4] + red[tid * 4 + 1] +
                       red[tid * 4 + 2] + red[tid * 4 + 3] + __ldg(b3 + t);
            out[(size_t)(gb0 + tid) * Tdim + t] = s4;
        }
    }
}

}  // namespace

extern "C" void kernel_launch(void* const* d_in, const int* in_sizes, int n_in,
                              void* d_out, int out_size) {
    const float* x  = (const float*)d_in[0];
    const float* W1 = (const float*)d_in[1];
    const float* b1 = (const float*)d_in[2];
    const float* W2 = (const float*)d_in[3];
    const float* b2 = (const float*)d_in[4];
    const float* W3 = (const float*)d_in[5];
    const float* b3 = (const float*)d_in[6];
    float* out = (float*)d_out;

    const int nx  = Bdim * INdim / 4;
    const int nw1 = Tdim * INdim * Hdim / 4;
    const int nw2 = Tdim * Hdim * Hdim / 4;
    split_kernel<<<(nx  + 255) / 256, 256>>>((const float4*)x,  0, nx);
    split_kernel<<<(nw1 + 255) / 256, 256>>>((const float4*)W1, 1, nw1);
    split_kernel<<<(nw2 + 255) / 256, 256>>>((const float4*)W2, 2, nw2);

    cudaFuncSetAttribute(mlp_hmma_kernel,
                         cudaFuncAttributeMaxDynamicSharedMemorySize, SMEM_TOTAL);
    dim3 grid(Bdim / MT, Tdim);  // b-block fastest: wave shares few tasks' W in L2
    mlp_hmma_kernel<<<grid, NTHR, SMEM_TOTAL>>>(b1, b2, W3, b3, out);
}